// round 14
// baseline (speedup 1.0000x reference)
#include <cuda_runtime.h>
#include <cuda_bf16.h>
#include <math.h>
#include <stdint.h>

typedef unsigned long long ull;

// ---- scratch (device globals; referenced ONLY inside device code) ----------
#define NMAX 100000
#define NPAD 100096              /* 782 * 128 (mma tile padding) */
#define EMAX 1600000
__device__ __align__(16) __nv_bfloat16 g_Hb[NPAD * 128];   // H (bf16)
__device__ __align__(16) __nv_bfloat16 g_AGb[NPAD * 128];  // agg result (bf16)
__device__ float  g_dinv[NMAX];                    // rsqrt(weighted degree)
__device__ int    g_cnt[NMAX];                     // in-degree counts
__device__ int    g_rowptr[NMAX + 1];              // CSR row pointers (by dst)
__device__ int    g_pos[NMAX];                     // scatter cursors
__device__ __align__(16) float2 g_edge[EMAX];      // {src_bits, coeff} by dst
__device__ int    g_is64;                          // edge_index is int64?

// ---- bf16 warp mma m16n8k16 (plain sm_103-legal, sm_80+ PTX) ---------------
__device__ __forceinline__ void mma16(float* d, const uint32_t* a,
                                      const uint32_t* b) {
    asm volatile(
        "mma.sync.aligned.m16n8k16.row.col.f32.bf16.bf16.f32 "
        "{%0,%1,%2,%3}, {%4,%5,%6,%7}, {%8,%9}, {%0,%1,%2,%3};"
        : "+f"(d[0]), "+f"(d[1]), "+f"(d[2]), "+f"(d[3])
        : "r"(a[0]), "r"(a[1]), "r"(a[2]), "r"(a[3]), "r"(b[0]), "r"(b[1]));
}

// bf16 gather: 4 features (8 bytes), converted to fp32
__device__ __forceinline__ float4 ldbf4(const __nv_bfloat16* base, int row,
                                        int lane) {
    uint2 u = *(const uint2*)(base + (size_t)row * 128 + lane * 4);
    float2 f0 = __bfloat1622float2(*(__nv_bfloat162*)&u.x);
    float2 f1 = __bfloat1622float2(*(__nv_bfloat162*)&u.y);
    return make_float4(f0.x, f0.y, f1.x, f1.y);
}
__device__ __forceinline__ void fma4(float4& acc, float c, const float4& v) {
    acc.x = fmaf(c, v.x, acc.x);
    acc.y = fmaf(c, v.y, acc.y);
    acc.z = fmaf(c, v.z, acc.z);
    acc.w = fmaf(c, v.w, acc.w);
}
__device__ __forceinline__ uint2 pack_bf4(float4 v) {
    __nv_bfloat162 p0 = __floats2bfloat162_rn(v.x, v.y);
    __nv_bfloat162 p1 = __floats2bfloat162_rn(v.z, v.w);
    return make_uint2(*(uint32_t*)&p0, *(uint32_t*)&p1);
}

// ---- edge-index dtype detection --------------------------------------------
__global__ void detect_kernel(const int* ei32, int twoE) {
    __shared__ int any;
    if (threadIdx.x == 0) any = 0;
    __syncthreads();
    int lim = twoE < 8192 ? twoE : 8192;
    for (int i = threadIdx.x * 2 + 1; i < lim; i += 512)
        if (ei32[i] != 0) any = 1;
    __syncthreads();
    if (threadIdx.x == 0) g_is64 = (any == 0) ? 1 : 0;
}

__device__ __forceinline__ void load_edge(const void* ei, int E, int e,
                                          int& r, int& c) {
    if (g_is64) {
        const long long* p = (const long long*)ei;
        r = (int)p[e];
        c = (int)p[(size_t)E + e];
    } else {
        const int* p = (const int*)ei;
        r = p[e];
        c = p[(size_t)E + e];
    }
}

// ---- degree + histogram ------------------------------------------------------
__global__ void deg_init_kernel(int n) {
    int i = blockIdx.x * blockDim.x + threadIdx.x;
    if (i < n) { g_dinv[i] = 1.0f; g_cnt[i] = 0; }
}

__global__ void deg_accum_kernel(const void* ei, const float* w, int E) {
    int e = blockIdx.x * blockDim.x + threadIdx.x;
    if (e < E) {
        int r, c;
        load_edge(ei, E, e, r, c);
        atomicAdd(&g_dinv[c], w[e]);
        atomicAdd(&g_cnt[c], 1);
    }
}

__global__ void deg_fin_kernel(int n) {
    int i = blockIdx.x * blockDim.x + threadIdx.x;
    if (i < n) {
        float d = g_dinv[i];
        float r = rsqrtf(d);
        r = r * (1.5f - 0.5f * d * r * r);
        g_dinv[i] = r;
    }
}

// ---- single-block exclusive scan of g_cnt -> g_rowptr, g_pos ----------------
__global__ __launch_bounds__(1024)
void scan_kernel(int n) {
    __shared__ int bsum[1024];
    int t = threadIdx.x;
    int chunk = (n + 1023) / 1024;
    int s = t * chunk;
    int e = min(s + chunk, n);
    int sum = 0;
    for (int i = s; i < e; i++) sum += g_cnt[i];
    bsum[t] = sum;
    __syncthreads();
    for (int off = 1; off < 1024; off <<= 1) {
        int v = 0;
        if (t >= off) v = bsum[t - off];
        __syncthreads();
        if (t >= off) bsum[t] += v;
        __syncthreads();
    }
    int run = (t == 0) ? 0 : bsum[t - 1];
    for (int i = s; i < e; i++) {
        g_rowptr[i] = run;
        g_pos[i] = run;
        run += g_cnt[i];
    }
    if (t == 1023 || e == n) g_rowptr[n] = bsum[1023];
}

// ---- scatter edges into CSR, precompute coeff --------------------------------
__global__ void scatter_kernel(const void* ei, const float* w, int E) {
    int e = blockIdx.x * blockDim.x + threadIdx.x;
    if (e >= E) return;
    int r, c;
    load_edge(ei, E, e, r, c);
    float coeff = g_dinv[r] * __ldg(&w[e]) * g_dinv[c];
    int p = atomicAdd(&g_pos[c], 1);
    g_edge[p] = make_float2(__int_as_float(r), coeff);
}

// ==== bf16 warp-MMA GEMM: g_Hb[128-tile] = f(X)[128,128] @ W[128,128] =======
// 8 warps; warp tile 32(M)x64(N); m16n8k16; full K=128 staged once in bf16.
// LDK=136 bf16 -> row stride 68 words -> all fragment LDS conflict-free.
// XSEL: 0 = Xarg (fp32), 1 = g_AGb (bf16). IN_RELU: relu(X + in_bias).
template <int XSEL, bool IN_RELU>
__global__ __launch_bounds__(256, 2)
void mma_gemm_kernel(const float* Xarg, const float* W,
                     const float* in_bias, int n) {
    constexpr int LDK = 136;
    extern __shared__ __align__(16) __nv_bfloat16 smem_bf[];
    __nv_bfloat16* xs = smem_bf;                 // [128 rows][LDK]
    __nv_bfloat16* ws = smem_bf + 128 * LDK;     // [128 cols][LDK]

    const int tid = threadIdx.x;
    const int node0 = blockIdx.x * 128;

    const int wid = tid >> 5;
    const int lane = tid & 31;
    const int g = lane >> 2;
    const int q = lane & 3;
    const int wm = wid & 3;
    const int wn = wid >> 2;

    // stage X (128 x 128, relu+bias fused, bf16)
    for (int i = tid; i < 128 * 32; i += 256) {
        int row = i >> 5;
        int k4 = (i & 31) * 4;
        float4 v = make_float4(0.f, 0.f, 0.f, 0.f);
        int gn = node0 + row;
        if (gn < n) {
            if (XSEL == 0) {
                v = *(const float4*)(Xarg + (size_t)gn * 128 + k4);
            } else {
                uint2 u = *(const uint2*)(g_AGb + (size_t)gn * 128 + k4);
                float2 f0 = __bfloat1622float2(*(__nv_bfloat162*)&u.x);
                float2 f1 = __bfloat1622float2(*(__nv_bfloat162*)&u.y);
                v = make_float4(f0.x, f0.y, f1.x, f1.y);
            }
            if (IN_RELU) {
                float4 bb = *(const float4*)(in_bias + k4);
                v.x = fmaxf(v.x + bb.x, 0.f);
                v.y = fmaxf(v.y + bb.y, 0.f);
                v.z = fmaxf(v.z + bb.z, 0.f);
                v.w = fmaxf(v.w + bb.w, 0.f);
            }
        }
        *(uint2*)(xs + row * LDK + k4) = pack_bf4(v);
    }
    // stage W transposed: ws[c][k] = bf16(W[k][c])
    for (int i = tid; i < 32 * 128; i += 256) {
        int kq = i >> 7;         // 0..31
        int c = i & 127;
#pragma unroll
        for (int j = 0; j < 4; j++) {
            int k = kq * 4 + j;
            ws[c * LDK + k] = __float2bfloat16(W[(size_t)k * 128 + c]);
        }
    }
    __syncthreads();

    float acc[2][8][4];
#pragma unroll
    for (int mt = 0; mt < 2; mt++)
#pragma unroll
        for (int nt = 0; nt < 8; nt++)
#pragma unroll
            for (int r = 0; r < 4; r++) acc[mt][nt][r] = 0.f;

#pragma unroll 1
    for (int k0 = 0; k0 < 128; k0 += 16) {
        uint32_t a[2][4];
#pragma unroll
        for (int mt = 0; mt < 2; mt++) {
            const __nv_bfloat16* xr = xs + (wm * 32 + mt * 16 + g) * LDK
                                         + k0 + 2 * q;
            a[mt][0] = *(const uint32_t*)xr;
            a[mt][1] = *(const uint32_t*)(xr + 8 * LDK);
            a[mt][2] = *(const uint32_t*)(xr + 8);
            a[mt][3] = *(const uint32_t*)(xr + 8 * LDK + 8);
        }
        uint32_t b[8][2];
#pragma unroll
        for (int nt = 0; nt < 8; nt++) {
            const __nv_bfloat16* wr = ws + (wn * 64 + nt * 8 + g) * LDK
                                         + k0 + 2 * q;
            b[nt][0] = *(const uint32_t*)wr;
            b[nt][1] = *(const uint32_t*)(wr + 8);
        }
#pragma unroll
        for (int mt = 0; mt < 2; mt++)
#pragma unroll
            for (int nt = 0; nt < 8; nt++)
                mma16(acc[mt][nt], a[mt], b[nt]);
    }

    // epilogue: bf16 stores; NPAD padding makes tail stores harmless
#pragma unroll
    for (int mt = 0; mt < 2; mt++) {
        int row = node0 + wm * 32 + mt * 16 + g;
#pragma unroll
        for (int nt = 0; nt < 8; nt++) {
            int col = wn * 64 + nt * 8 + q * 2;
            *(__nv_bfloat162*)(g_Hb + (size_t)row * 128 + col) =
                __floats2bfloat162_rn(acc[mt][nt][0], acc[mt][nt][1]);
            *(__nv_bfloat162*)(g_Hb + (size_t)(row + 8) * 128 + col) =
                __floats2bfloat162_rn(acc[mt][nt][2], acc[mt][nt][3]);
        }
    }
}

// ==== bf16 warp-MMA fc: d_out = sigmoid(relu(g_AGb+b2)[N,128]@Wfc[128,64]+bfc)
// tile M=128 x N=64; 8 warps = 4M x 2N; warp tile 32x32.
__global__ __launch_bounds__(256, 2)
void fc_mma_kernel(const float* W, const float* in_bias,
                   const float* out_bias, float* OUT, int n) {
    constexpr int LDK = 136;
    extern __shared__ __align__(16) __nv_bfloat16 smem_bf[];
    __nv_bfloat16* xs = smem_bf;                 // [128 rows][LDK]
    __nv_bfloat16* ws = smem_bf + 128 * LDK;     // [64 cols][LDK]

    const int tid = threadIdx.x;
    const int node0 = blockIdx.x * 128;

    const int wid = tid >> 5;
    const int lane = tid & 31;
    const int g = lane >> 2;
    const int q = lane & 3;
    const int wm = wid & 3;
    const int wn = wid >> 2;

    for (int i = tid; i < 128 * 32; i += 256) {
        int row = i >> 5;
        int k4 = (i & 31) * 4;
        float4 v = make_float4(0.f, 0.f, 0.f, 0.f);
        int gn = node0 + row;
        if (gn < n) {
            uint2 u = *(const uint2*)(g_AGb + (size_t)gn * 128 + k4);
            float2 f0 = __bfloat1622float2(*(__nv_bfloat162*)&u.x);
            float2 f1 = __bfloat1622float2(*(__nv_bfloat162*)&u.y);
            float4 bb = *(const float4*)(in_bias + k4);
            v.x = fmaxf(f0.x + bb.x, 0.f);
            v.y = fmaxf(f0.y + bb.y, 0.f);
            v.z = fmaxf(f1.x + bb.z, 0.f);
            v.w = fmaxf(f1.y + bb.w, 0.f);
        }
        *(uint2*)(xs + row * LDK + k4) = pack_bf4(v);
    }
    for (int i = tid; i < 32 * 64; i += 256) {
        int kq = i >> 6;
        int c = i & 63;
#pragma unroll
        for (int j = 0; j < 4; j++) {
            int k = kq * 4 + j;
            ws[c * LDK + k] = __float2bfloat16(W[(size_t)k * 64 + c]);
        }
    }
    __syncthreads();

    float acc[2][4][4];
#pragma unroll
    for (int mt = 0; mt < 2; mt++)
#pragma unroll
        for (int nt = 0; nt < 4; nt++)
#pragma unroll
            for (int r = 0; r < 4; r++) acc[mt][nt][r] = 0.f;

#pragma unroll 1
    for (int k0 = 0; k0 < 128; k0 += 16) {
        uint32_t a[2][4];
#pragma unroll
        for (int mt = 0; mt < 2; mt++) {
            const __nv_bfloat16* xr = xs + (wm * 32 + mt * 16 + g) * LDK
                                         + k0 + 2 * q;
            a[mt][0] = *(const uint32_t*)xr;
            a[mt][1] = *(const uint32_t*)(xr + 8 * LDK);
            a[mt][2] = *(const uint32_t*)(xr + 8);
            a[mt][3] = *(const uint32_t*)(xr + 8 * LDK + 8);
        }
        uint32_t b[4][2];
#pragma unroll
        for (int nt = 0; nt < 4; nt++) {
            const __nv_bfloat16* wr = ws + (wn * 32 + nt * 8 + g) * LDK
                                         + k0 + 2 * q;
            b[nt][0] = *(const uint32_t*)wr;
            b[nt][1] = *(const uint32_t*)(wr + 8);
        }
#pragma unroll
        for (int mt = 0; mt < 2; mt++)
#pragma unroll
            for (int nt = 0; nt < 4; nt++)
                mma16(acc[mt][nt], a[mt], b[nt]);
    }

    // epilogue: +bfc, sigmoid, guarded fp32 stores (d_out unpadded)
#pragma unroll
    for (int mt = 0; mt < 2; mt++) {
        int row0 = node0 + wm * 32 + mt * 16 + g;
#pragma unroll
        for (int nt = 0; nt < 4; nt++) {
            int col = wn * 32 + nt * 8 + q * 2;
            float b0 = out_bias[col];
            float b1 = out_bias[col + 1];
            if (row0 < n) {
                float v0 = 1.f / (1.f + expf(-(acc[mt][nt][0] + b0)));
                float v1 = 1.f / (1.f + expf(-(acc[mt][nt][1] + b1)));
                *(float2*)(OUT + (size_t)row0 * 64 + col) = make_float2(v0, v1);
            }
            if (row0 + 8 < n) {
                float v2 = 1.f / (1.f + expf(-(acc[mt][nt][2] + b0)));
                float v3 = 1.f / (1.f + expf(-(acc[mt][nt][3] + b1)));
                *(float2*)(OUT + (size_t)(row0 + 8) * 64 + col) =
                    make_float2(v2, v3);
            }
        }
    }
}

// ---- CSR aggregation (bf16 gathers, fp32 accumulate, bf16 store) -----------
__global__ __launch_bounds__(256)
void agg_csr_kernel(int n) {
    int gid = blockIdx.x * blockDim.x + threadIdx.x;
    int node = gid >> 5;
    if (node >= n) return;
    int lane = gid & 31;

    int beg = g_rowptr[node];
    int end = g_rowptr[node + 1];

    float d = g_dinv[node];
    float s = d * d;
    float4 acc = ldbf4(g_Hb, node, lane);
    acc.x *= s; acc.y *= s; acc.z *= s; acc.w *= s;

    int j = beg;
    for (; j + 3 < end; j += 4) {
        float2 e0 = g_edge[j];
        float2 e1 = g_edge[j + 1];
        float2 e2 = g_edge[j + 2];
        float2 e3 = g_edge[j + 3];
        float4 v0 = ldbf4(g_Hb, __float_as_int(e0.x), lane);
        float4 v1 = ldbf4(g_Hb, __float_as_int(e1.x), lane);
        float4 v2 = ldbf4(g_Hb, __float_as_int(e2.x), lane);
        float4 v3 = ldbf4(g_Hb, __float_as_int(e3.x), lane);
        fma4(acc, e0.y, v0);
        fma4(acc, e1.y, v1);
        fma4(acc, e2.y, v2);
        fma4(acc, e3.y, v3);
    }
    for (; j < end; j++) {
        float2 e0 = g_edge[j];
        float4 v0 = ldbf4(g_Hb, __float_as_int(e0.x), lane);
        fma4(acc, e0.y, v0);
    }

    *(uint2*)(g_AGb + (size_t)node * 128 + lane * 4) = pack_bf4(acc);
}

// ---- launch -------------------------------------------------------------------
extern "C" void kernel_launch(void* const* d_in, const int* in_sizes, int n_in,
                              void* d_out, int out_size) {
    const float* x   = (const float*)d_in[0];
    const void*  ei  = d_in[1];
    const float* ew  = (const float*)d_in[2];
    const float* W1  = (const float*)d_in[3];
    const float* b1  = (const float*)d_in[4];
    const float* W2  = (const float*)d_in[5];
    const float* b2  = (const float*)d_in[6];
    const float* Wfc = (const float*)d_in[7];
    const float* bfc = (const float*)d_in[8];

    int N = in_sizes[0] / 128;
    int E = in_sizes[2];

    int gb128 = (N + 127) / 128;
    int awarps = (N * 32 + 255) / 256;
    int eb = (E + 255) / 256;
    int nb = (N + 255) / 256;

    const int MMA_SMEM = 2 * 128 * 136 * 2;        // 69632 B
    const int FC_SMEM = (128 + 64) * 136 * 2;      // 52224 B
    cudaFuncSetAttribute(mma_gemm_kernel<0, false>,
                         cudaFuncAttributeMaxDynamicSharedMemorySize, MMA_SMEM);
    cudaFuncSetAttribute(mma_gemm_kernel<1, true>,
                         cudaFuncAttributeMaxDynamicSharedMemorySize, MMA_SMEM);
    cudaFuncSetAttribute(fc_mma_kernel,
                         cudaFuncAttributeMaxDynamicSharedMemorySize, FC_SMEM);

    // fork side stream: CSR build overlaps layer-1 GEMM
    cudaStream_t s2;
    cudaStreamCreateWithFlags(&s2, cudaStreamNonBlocking);
    cudaEvent_t evF, evJ;
    cudaEventCreateWithFlags(&evF, cudaEventDisableTiming);
    cudaEventCreateWithFlags(&evJ, cudaEventDisableTiming);

    cudaEventRecord(evF, 0);
    cudaStreamWaitEvent(s2, evF, 0);

    detect_kernel<<<1, 256, 0, s2>>>((const int*)ei, 2 * E);
    deg_init_kernel<<<nb, 256, 0, s2>>>(N);
    deg_accum_kernel<<<eb, 256, 0, s2>>>(ei, ew, E);
    deg_fin_kernel<<<nb, 256, 0, s2>>>(N);
    scan_kernel<<<1, 1024, 0, s2>>>(N);
    scatter_kernel<<<eb, 256, 0, s2>>>(ei, ew, E);
    cudaEventRecord(evJ, s2);

    // layer 1: Hb = x@W1 (bf16 warp-mma)
    mma_gemm_kernel<0, false><<<gb128, 256, MMA_SMEM>>>(x, W1, nullptr, N);
    cudaStreamWaitEvent(0, evJ, 0);
    agg_csr_kernel<<<awarps, 256>>>(N);

    // layer 2: Hb = relu(g_AGb + b1)@W2 (bf16 warp-mma)
    mma_gemm_kernel<1, true><<<gb128, 256, MMA_SMEM>>>(nullptr, W2, b1, N);
    agg_csr_kernel<<<awarps, 256>>>(N);

    // final: d_out = sigmoid( relu(g_AGb + b2) @ Wfc + bfc )  (bf16 warp-mma)
    fc_mma_kernel<<<gb128, 256, FC_SMEM>>>(Wfc, b2, bfc, (float*)d_out, N);
}